// round 1
// baseline (speedup 1.0000x reference)
#include <cuda_runtime.h>
#include <cstdint>

#define N_ATOMS 100000
#define N_EDGES 400000
#define N_MOLS  4096
#define ATOM_FDIM 133
#define BOND_FDIM 14
#define HIDDEN 300
#define N_LABELS 12
#define NPAD 320        // padded hidden width
#define KX 136          // padded atom feature dim
#define KE 16           // padded bond feature dim
#define KH 304          // padded hidden as K-dim

// ------------------------- scratch (static, no allocs) -------------------------
__device__ float g_xpad[(size_t)N_ATOMS * KX];
__device__ float g_eapad[(size_t)N_EDGES * KE];
__device__ float g_hv  [(size_t)N_ATOMS * NPAD];
__device__ float g_hv2 [(size_t)N_ATOMS * NPAD];
__device__ float g_P   [(size_t)N_ATOMS * NPAD];
__device__ float g_agg [(size_t)N_ATOMS * NPAD];
__device__ float g_E   [(size_t)N_EDGES * NPAD];
__device__ float g_mol [(size_t)N_MOLS * NPAD];
__device__ float g_ffn [(size_t)N_MOLS * NPAD];

__device__ float g_atomW[KX * NPAD];
__device__ float g_WiTop[KH * NPAD];
__device__ float g_WiBot[KE * NPAD];
__device__ float g_Wo   [2 * KH * NPAD];
__device__ float g_ffn1 [KH * NPAD];
__device__ float g_atomB[NPAD];
__device__ float g_WoB  [NPAD];
__device__ float g_ffn1B[NPAD];
__device__ float g_zeros[NPAD];   // stays zero

// ------------------------- helpers -------------------------
__device__ __forceinline__ unsigned long long pack2(float x) {
    unsigned long long r;
    asm("mov.b64 %0, {%1, %1};" : "=l"(r) : "f"(x));
    return r;
}

union U64F2 { unsigned long long u; float2 f; };

// ------------------------- repack: zero-padded copy -------------------------
__global__ void repack(float* __restrict__ dst, const float* __restrict__ src,
                       int dstR, int dstC, int srcR, int srcC, int srcRow0) {
    int idx = blockIdx.x * blockDim.x + threadIdx.x;
    if (idx >= dstR * dstC) return;
    int r = idx / dstC, c = idx - r * dstC;
    float v = 0.f;
    if (r < srcR && c < srcC) v = src[(size_t)(r + srcRow0) * srcC + c];
    dst[idx] = v;
}

__global__ void zerok(float4* __restrict__ p, int n4) {
    int i = blockIdx.x * blockDim.x + threadIdx.x;
    if (i < n4) p[i] = make_float4(0.f, 0.f, 0.f, 0.f);
}

// ------------------------- GEMM: C[M x 320] = relu?(A @ W + bias) -------------------------
// A is a virtual concat of A1 (K1 cols, stride lda1) and A2 (K2 cols, stride lda2).
// K1, K2 multiples of 8. W padded [K1+K2 x 320]. Uses packed fp32x2 FMA.
__global__ __launch_bounds__(256)
void gemm320(const float* __restrict__ A1, int lda1, int K1,
             const float* __restrict__ A2, int lda2, int K2,
             const float* __restrict__ W, const float* __restrict__ bias,
             float* __restrict__ C, int M, int doRelu) {
    __shared__ float As[8][64];
    __shared__ float Bs[8][NPAD];

    int tid = threadIdx.x;
    int tx = tid & 15;      // column group (handles cols tx*2 + j*32, j=0..9)
    int ty = tid >> 4;      // row group (4 rows each)
    int row0 = blockIdx.x * 64;

    unsigned long long acc[4][10];
    #pragma unroll
    for (int m = 0; m < 4; m++)
        #pragma unroll
        for (int j = 0; j < 10; j++) acc[m][j] = 0ULL;

    int Ktot = K1 + K2;
    int ar = tid >> 2;            // 0..63 : A-tile row
    int ak = (tid & 3) * 2;       // 0,2,4,6 : A-tile k pair

    for (int k0 = 0; k0 < Ktot; k0 += 8) {
        // --- load A tile (64 x 8) ---
        const float* Asrc; int lda; int kb;
        if (k0 < K1) { Asrc = A1; lda = lda1; kb = k0; }
        else         { Asrc = A2; lda = lda2; kb = k0 - K1; }
        float2 av = make_float2(0.f, 0.f);
        int grow = row0 + ar;
        if (grow < M) av = *(const float2*)(Asrc + (size_t)grow * lda + kb + ak);
        As[ak][ar] = av.x;
        As[ak + 1][ar] = av.y;
        // --- load B tile (8 x 320) ---
        const float2* Wsrc = (const float2*)(W + (size_t)k0 * NPAD);
        #pragma unroll
        for (int i = 0; i < 5; i++) {
            int idx = tid + i * 256;            // 0..1279 float2
            int bk = idx / 160;
            int bn = idx - bk * 160;
            float2 v = Wsrc[(size_t)bk * 160 + bn];
            *(float2*)&Bs[bk][bn * 2] = v;
        }
        __syncthreads();
        #pragma unroll
        for (int k = 0; k < 8; k++) {
            float4 a4 = *(const float4*)&As[k][ty * 4];
            unsigned long long b[10];
            #pragma unroll
            for (int j = 0; j < 10; j++)
                b[j] = *(const unsigned long long*)&Bs[k][(tx + j * 16) * 2];
            unsigned long long a2[4];
            a2[0] = pack2(a4.x); a2[1] = pack2(a4.y);
            a2[2] = pack2(a4.z); a2[3] = pack2(a4.w);
            #pragma unroll
            for (int m = 0; m < 4; m++)
                #pragma unroll
                for (int j = 0; j < 10; j++)
                    asm("fma.rn.f32x2 %0, %1, %2, %0;"
                        : "+l"(acc[m][j]) : "l"(a2[m]), "l"(b[j]));
        }
        __syncthreads();
    }

    #pragma unroll
    for (int m = 0; m < 4; m++) {
        int grow = row0 + ty * 4 + m;
        if (grow < M) {
            #pragma unroll
            for (int j = 0; j < 10; j++) {
                int col = (tx + j * 16) * 2;
                U64F2 u; u.u = acc[m][j];
                float2 v = u.f;
                float2 bv = *(const float2*)&bias[col];
                v.x += bv.x; v.y += bv.y;
                if (doRelu) { v.x = fmaxf(v.x, 0.f); v.y = fmaxf(v.y, 0.f); }
                *(float2*)(C + (size_t)grow * NPAD + col) = v;
            }
        }
    }
}

// ------------------------- edge scatter: agg[dst] += relu(P[src] + E[e]) -------------------------
__global__ void edge_scatter(const float* __restrict__ P, const float* __restrict__ E,
                             const int* __restrict__ src, const int* __restrict__ dst,
                             float* __restrict__ agg) {
    int w = (blockIdx.x * blockDim.x + threadIdx.x) >> 5;
    int lane = threadIdx.x & 31;
    if (w >= N_EDGES) return;
    int s = src[w], d = dst[w];
    const float4* Pr = (const float4*)(P + (size_t)s * NPAD);
    const float4* Er = (const float4*)(E + (size_t)w * NPAD);
    float* ag = agg + (size_t)d * NPAD;
    for (int c = lane; c < 75; c += 32) {      // 300 valid cols = 75 float4
        float4 p = Pr[c];
        float4 e = Er[c];
        float x0 = fmaxf(p.x + e.x, 0.f);
        float x1 = fmaxf(p.y + e.y, 0.f);
        float x2 = fmaxf(p.z + e.z, 0.f);
        float x3 = fmaxf(p.w + e.w, 0.f);
        atomicAdd(ag + 4 * c + 0, x0);
        atomicAdd(ag + 4 * c + 1, x1);
        atomicAdd(ag + 4 * c + 2, x2);
        atomicAdd(ag + 4 * c + 3, x3);
    }
}

// ------------------------- mol scatter: mol[batch[a]] += h_v[a] -------------------------
__global__ void mol_scatter(const float* __restrict__ hv, const int* __restrict__ batch,
                            float* __restrict__ mol) {
    int w = (blockIdx.x * blockDim.x + threadIdx.x) >> 5;
    int lane = threadIdx.x & 31;
    if (w >= N_ATOMS) return;
    int b = batch[w];
    const float4* hr = (const float4*)(hv + (size_t)w * NPAD);
    float* mr = mol + (size_t)b * NPAD;
    for (int c = lane; c < 75; c += 32) {
        float4 v = hr[c];
        atomicAdd(mr + 4 * c + 0, v.x);
        atomicAdd(mr + 4 * c + 1, v.y);
        atomicAdd(mr + 4 * c + 2, v.z);
        atomicAdd(mr + 4 * c + 3, v.w);
    }
}

// ------------------------- final: out = relu'd_ffn @ ffn2 + b2 -------------------------
__global__ void finalk(const float* __restrict__ F, const float* __restrict__ W2,
                       const float* __restrict__ b2, float* __restrict__ out) {
    int w = (blockIdx.x * blockDim.x + threadIdx.x) >> 5;
    int lane = threadIdx.x & 31;
    if (w >= N_MOLS) return;
    float acc = (lane < 12) ? b2[lane] : 0.f;
    const float* f = F + (size_t)w * NPAD;
    for (int j = 0; j < HIDDEN; j++) {
        float fv = __ldg(f + j);
        if (lane < 12) acc = fmaf(fv, W2[j * 12 + lane], acc);
    }
    if (lane < 12) out[w * 12 + lane] = acc;
}

// ------------------------- host launch -------------------------
static inline dim3 rep_grid(int n) { return dim3((n + 255) / 256); }

extern "C" void kernel_launch(void* const* d_in, const int* in_sizes, int n_in,
                              void* d_out, int out_size) {
    const float* x      = (const float*)d_in[0];
    const int*   ei     = (const int*)  d_in[1];   // [2, N_EDGES]
    const float* ea     = (const float*)d_in[2];
    const int*   batch  = (const int*)  d_in[3];
    const float* atom_W = (const float*)d_in[4];
    const float* atom_b = (const float*)d_in[5];
    // d_in[6], d_in[7]: bond_W / bond_b  -> dead code
    const float* Wi     = (const float*)d_in[8];
    // d_in[9]: Wh -> dead code
    const float* Wo     = (const float*)d_in[10];
    const float* Wo_b   = (const float*)d_in[11];
    const float* ffn1_W = (const float*)d_in[12];
    const float* ffn1_b = (const float*)d_in[13];
    const float* ffn2_W = (const float*)d_in[14];
    const float* ffn2_b = (const float*)d_in[15];
    float* out = (float*)d_out;

    float *p_xpad, *p_eapad, *p_hv, *p_hv2, *p_P, *p_agg, *p_E, *p_mol, *p_ffn;
    float *p_atomW, *p_WiTop, *p_WiBot, *p_Wo, *p_ffn1;
    float *p_atomB, *p_WoB, *p_ffn1B, *p_zeros;
    cudaGetSymbolAddress((void**)&p_xpad,  g_xpad);
    cudaGetSymbolAddress((void**)&p_eapad, g_eapad);
    cudaGetSymbolAddress((void**)&p_hv,    g_hv);
    cudaGetSymbolAddress((void**)&p_hv2,   g_hv2);
    cudaGetSymbolAddress((void**)&p_P,     g_P);
    cudaGetSymbolAddress((void**)&p_agg,   g_agg);
    cudaGetSymbolAddress((void**)&p_E,     g_E);
    cudaGetSymbolAddress((void**)&p_mol,   g_mol);
    cudaGetSymbolAddress((void**)&p_ffn,   g_ffn);
    cudaGetSymbolAddress((void**)&p_atomW, g_atomW);
    cudaGetSymbolAddress((void**)&p_WiTop, g_WiTop);
    cudaGetSymbolAddress((void**)&p_WiBot, g_WiBot);
    cudaGetSymbolAddress((void**)&p_Wo,    g_Wo);
    cudaGetSymbolAddress((void**)&p_ffn1,  g_ffn1);
    cudaGetSymbolAddress((void**)&p_atomB, g_atomB);
    cudaGetSymbolAddress((void**)&p_WoB,   g_WoB);
    cudaGetSymbolAddress((void**)&p_ffn1B, g_ffn1B);
    cudaGetSymbolAddress((void**)&p_zeros, g_zeros);

    // ---- repack inputs / weights into padded layouts ----
    repack<<<rep_grid(N_ATOMS * KX), 256>>>(p_xpad, x, N_ATOMS, KX, N_ATOMS, ATOM_FDIM, 0);
    repack<<<rep_grid(N_EDGES * KE), 256>>>(p_eapad, ea, N_EDGES, KE, N_EDGES, BOND_FDIM, 0);
    repack<<<rep_grid(KX * NPAD), 256>>>(p_atomW, atom_W, KX, NPAD, ATOM_FDIM, HIDDEN, 0);
    repack<<<rep_grid(KH * NPAD), 256>>>(p_WiTop, Wi, KH, NPAD, HIDDEN, HIDDEN, 0);
    repack<<<rep_grid(KE * NPAD), 256>>>(p_WiBot, Wi, KE, NPAD, BOND_FDIM, HIDDEN, HIDDEN);
    repack<<<rep_grid(KH * NPAD), 256>>>(p_Wo, Wo, KH, NPAD, HIDDEN, HIDDEN, 0);
    repack<<<rep_grid(KH * NPAD), 256>>>(p_Wo + KH * NPAD, Wo, KH, NPAD, HIDDEN, HIDDEN, HIDDEN);
    repack<<<rep_grid(KH * NPAD), 256>>>(p_ffn1, ffn1_W, KH, NPAD, HIDDEN, HIDDEN, 0);
    repack<<<rep_grid(NPAD), 256>>>(p_atomB, atom_b, 1, NPAD, 1, HIDDEN, 0);
    repack<<<rep_grid(NPAD), 256>>>(p_WoB, Wo_b, 1, NPAD, 1, HIDDEN, 0);
    repack<<<rep_grid(NPAD), 256>>>(p_ffn1B, ffn1_b, 1, NPAD, 1, HIDDEN, 0);

    dim3 gAtom((N_ATOMS + 63) / 64), gEdge((N_EDGES + 63) / 64), gMol((N_MOLS + 63) / 64);

    // h_v = relu(x @ atom_W + atom_b)
    gemm320<<<gAtom, 256>>>(p_xpad, KX, KX, nullptr, 0, 0, p_atomW, p_atomB, p_hv, N_ATOMS, 1);
    // E = edge_attr @ Wi_bot   (loop-invariant)
    gemm320<<<gEdge, 256>>>(p_eapad, KE, KE, nullptr, 0, 0, p_WiBot, p_zeros, p_E, N_EDGES, 0);

    int edge_blocks = (N_EDGES * 32 + 255) / 256;
    int atom_warp_blocks = (N_ATOMS * 32 + 255) / 256;

    float* cur = p_hv;
    float* nxt = p_hv2;
    for (int d = 0; d < 3; d++) {
        // P = h_v @ Wi_top
        gemm320<<<gAtom, 256>>>(cur, NPAD, KH, nullptr, 0, 0, p_WiTop, p_zeros, p_P, N_ATOMS, 0);
        // agg = 0; agg[dst] += relu(P[src] + E)
        zerok<<<(N_ATOMS * NPAD / 4 + 255) / 256, 256>>>((float4*)p_agg, N_ATOMS * NPAD / 4);
        edge_scatter<<<edge_blocks, 256>>>(p_P, p_E, ei, ei + N_EDGES, p_agg);
        // h_v = relu([h_v, agg] @ Wo + Wo_b)
        gemm320<<<gAtom, 256>>>(cur, NPAD, KH, p_agg, NPAD, KH, p_Wo, p_WoB, nxt, N_ATOMS, 1);
        float* t = cur; cur = nxt; nxt = t;
    }

    // mol_repr = segment_sum(h_v, batch)
    zerok<<<(N_MOLS * NPAD / 4 + 255) / 256, 256>>>((float4*)p_mol, N_MOLS * NPAD / 4);
    mol_scatter<<<atom_warp_blocks, 256>>>(cur, batch, p_mol);
    // ffn = relu(mol @ ffn1 + b1)
    gemm320<<<gMol, 256>>>(p_mol, NPAD, KH, nullptr, 0, 0, p_ffn1, p_ffn1B, p_ffn, N_MOLS, 1);
    // out = ffn @ ffn2 + b2
    finalk<<<(N_MOLS * 32 + 255) / 256, 256>>>(p_ffn, ffn2_W, ffn2_b, out);
}